// round 12
// baseline (speedup 1.0000x reference)
#include <cuda_runtime.h>

#define NN 50000
#define EE 800000
#define GG 500
#define CH 128
#define EF 16
#define NL 4
#define NC 10
#define BN_EPS 1e-5f

#define NWARP 16
#define THREADS (NWARP * 32)   // 512
#define TILE 128               // rows per block tile (8 strips of 16)
#define XST 132                // xs row stride in floats (bank-skewed)
#define WFRAG_N (16 * 16 * 32 * 2)   // 16384 u32 entries PER hi/lo array

#define CVT_TF32(u, f) asm("cvt.rna.tf32.f32 %0, %1;" : "=r"(u) : "f"(f))

#define MMA_TF32(d, a0, a1, a2, a3, b0, b1)                                  \
    asm volatile("mma.sync.aligned.m16n8k8.row.col.f32.tf32.tf32.f32 "       \
        "{%0,%1,%2,%3}, {%4,%5,%6,%7}, {%8,%9}, {%0,%1,%2,%3};"              \
        : "+f"(d[0]), "+f"(d[1]), "+f"(d[2]), "+f"(d[3])                     \
        : "r"(a0), "r"(a1), "r"(a2), "r"(a3), "r"(b0), "r"(b1))

// pairwise named barrier: 2 warps (64 threads) of strip s
#define PAIR_BAR(s) asm volatile("bar.sync %0, 64;" :: "r"((s) + 1) : "memory")

// ------------------------- scratch (device globals, no allocation) ---------
__device__ __align__(16) float g_h[NN * CH];
__device__ __align__(16) float g_z[NN * CH];
__device__ __align__(16) float g_ea[NN * EF];
__device__ int   g_deg[NN];
__device__ int   g_rowptr[NN + 1];
__device__ int   g_cursor[NN];
__device__ int   g_col[EE];
__device__ int   g_eid[EE];
__device__ int   g_bsum[64];
__device__ __align__(16) float g_stats[NL * 2 * CH];
__device__ __align__(16) float g_pooled[(NL + 1) * GG * CH];

// ------------------------- degree count ------------------------------------
__global__ void k_deg(const int* __restrict__ ei) {
    int e = blockIdx.x * blockDim.x + threadIdx.x;
    if (e >= EE) return;
    atomicAdd(&g_deg[ei[EE + e]], 1);
}

// ------------------------- scan pass 1: per-block sums ---------------------
__global__ void k_scan1() {
    __shared__ int s[1024];
    int i = blockIdx.x * 1024 + threadIdx.x;
    s[threadIdx.x] = (i < NN) ? g_deg[i] : 0;
    __syncthreads();
    for (int off = 512; off > 0; off >>= 1) {
        if (threadIdx.x < off) s[threadIdx.x] += s[threadIdx.x + off];
        __syncthreads();
    }
    if (threadIdx.x == 0) g_bsum[blockIdx.x] = s[0];
}

// ------------- scan pass 2: per-block base + local scan --------------------
__global__ void k_scan3(int nb) {
    __shared__ int s[1024];
    __shared__ int base;
    if (threadIdx.x == 0) {
        int run = 0;
        for (int b = 0; b < blockIdx.x; b++) run += g_bsum[b];
        base = run;
        if (blockIdx.x == 0) g_rowptr[NN] = EE;
    }
    int i = blockIdx.x * 1024 + threadIdx.x;
    int v = (i < NN) ? g_deg[i] : 0;
    s[threadIdx.x] = v;
    __syncthreads();
    for (int off = 1; off < 1024; off <<= 1) {
        int t = (threadIdx.x >= off) ? s[threadIdx.x - off] : 0;
        __syncthreads();
        s[threadIdx.x] += t;
        __syncthreads();
    }
    if (i < NN) {
        int r = s[threadIdx.x] - v + base;
        g_rowptr[i] = r;
        g_cursor[i] = r;
    }
}

// ------------------------- CSR fill ----------------------------------------
__global__ void k_fill(const int* __restrict__ ei) {
    int e = blockIdx.x * blockDim.x + threadIdx.x;
    if (e >= EE) return;
    int d = ei[EE + e];
    int pos = atomicAdd(&g_cursor[d], 1);
    g_col[pos] = ei[e];
    g_eid[pos] = e;
}

// ------------------------- ea = segment_sum(edge_attr, dst) ----------------
__global__ void k_ea(const float* __restrict__ eattr) {
    int idx = blockIdx.x * blockDim.x + threadIdx.x;
    int n = idx >> 4;
    if (n >= NN) return;
    int k = idx & 15;
    int beg = g_rowptr[n], end = g_rowptr[n + 1];
    float a0 = 0.f, a1 = 0.f;
    int e = beg;
    for (; e + 2 <= end; e += 2) {
        int i0 = g_eid[e], i1 = g_eid[e + 1];
        a0 += eattr[(size_t)i0 * EF + k];
        a1 += eattr[(size_t)i1 * EF + k];
    }
    if (e < end) a0 += eattr[(size_t)g_eid[e] * EF + k];
    g_ea[(size_t)n * EF + k] = a0 + a1;
}

// ---- stage W into tf32 hi/lo fragment order: W{hi,lo}[kt][nt][lane][2] ----
__device__ __forceinline__ void stage_wfrag_hl(unsigned* __restrict__ Whi,
                                               unsigned* __restrict__ Wlo,
                                               const float* __restrict__ W,
                                               int tid, int nthr) {
    for (int i = tid; i < 16 * 16 * 32; i += nthr) {
        int ln = i & 31, nt = (i >> 5) & 15, kt = i >> 9;
        int t = ln & 3, g = ln >> 2;
        float w0 = W[(kt * 8 + t) * CH + nt * 8 + g];
        float w1 = W[(kt * 8 + t + 4) * CH + nt * 8 + g];
        unsigned h0, h1;
        CVT_TF32(h0, w0); CVT_TF32(h1, w1);
        Whi[2 * i] = h0;
        Whi[2 * i + 1] = h1;
        Wlo[2 * i]     = __float_as_uint(w0 - __uint_as_float(h0));
        Wlo[2 * i + 1] = __float_as_uint(w1 - __uint_as_float(h1));
    }
}

// ====== tensor-core strip GEMM: warp computes 16 rows x 64 cols (3xTF32) ===
// warp-pair 2s,2s+1 owns strip s; nh = warp&1 picks ntiles [8nh, 8nh+8).
// W pre-converted to tf32 hi/lo -> inner loop is LDS+MMA only.
// D = Xhi*Whi + Xhi*Wlo + Xlo*Whi.
template <bool STATS>
__device__ __forceinline__ void mma_strip(
    const unsigned* __restrict__ Whi, const unsigned* __restrict__ Wlo,
    const float* __restrict__ xs, const float* __restrict__ bs,
    float* __restrict__ Z, int tile, int warp, int lane,
    float* cs, float* cq) {
    const int s = warp >> 1, nh = warp & 1;
    const int g = lane >> 2, t = lane & 3;

    float d[8][4];
#pragma unroll
    for (int j = 0; j < 8; j++) {
        d[j][0] = 0.f; d[j][1] = 0.f; d[j][2] = 0.f; d[j][3] = 0.f;
    }

    const float* xA = xs + (s * 16 + g) * XST + t;
    const uint2* whb = (const uint2*)Whi + nh * 8 * 32 + lane;
    const uint2* wlb = (const uint2*)Wlo + nh * 8 * 32 + lane;

#pragma unroll 2
    for (int kt = 0; kt < 16; kt++) {
        float a0f = xA[kt * 8];
        float a1f = xA[kt * 8 + 8 * XST];
        float a2f = xA[kt * 8 + 4];
        float a3f = xA[kt * 8 + 8 * XST + 4];
        unsigned ah0, ah1, ah2, ah3;
        CVT_TF32(ah0, a0f); CVT_TF32(ah1, a1f);
        CVT_TF32(ah2, a2f); CVT_TF32(ah3, a3f);
        unsigned al0 = __float_as_uint(a0f - __uint_as_float(ah0));
        unsigned al1 = __float_as_uint(a1f - __uint_as_float(ah1));
        unsigned al2 = __float_as_uint(a2f - __uint_as_float(ah2));
        unsigned al3 = __float_as_uint(a3f - __uint_as_float(ah3));
        const uint2* wh = whb + kt * 512;
        const uint2* wl = wlb + kt * 512;
#pragma unroll
        for (int j = 0; j < 8; j++) {
            uint2 bh = wh[j * 32];
            uint2 bl = wl[j * 32];
            MMA_TF32(d[j], ah0, ah1, ah2, ah3, bh.x, bh.y);
            MMA_TF32(d[j], ah0, ah1, ah2, ah3, bl.x, bl.y);
            MMA_TF32(d[j], al0, al1, al2, al3, bh.x, bh.y);
        }
    }

#pragma unroll
    for (int j = 0; j < 8; j++) {
        int col = (nh * 8 + j) * 8 + 2 * t;
        float bx = bs[col], by = bs[col + 1];
        int m0 = tile + s * 16 + g;
        if (m0 < NN) {
            float2 o; o.x = d[j][0] + bx; o.y = d[j][1] + by;
            *(float2*)(Z + (size_t)m0 * CH + col) = o;
            if (STATS) {
                cs[2 * j] += o.x;     cq[2 * j] += o.x * o.x;
                cs[2 * j + 1] += o.y; cq[2 * j + 1] += o.y * o.y;
            }
        }
        if (m0 + 8 < NN) {
            float2 o; o.x = d[j][2] + bx; o.y = d[j][3] + by;
            *(float2*)(Z + (size_t)(m0 + 8) * CH + col) = o;
            if (STATS) {
                cs[2 * j] += o.x;     cq[2 * j] += o.x * o.x;
                cs[2 * j + 1] += o.y; cq[2 * j + 1] += o.y * o.y;
            }
        }
    }
}

// ------------------------- plain GEMM (embedding) ---------------------------
__global__ void __launch_bounds__(THREADS, 1)
k_gemm(const float* __restrict__ X, const float* __restrict__ W,
       const float* __restrict__ B, float* __restrict__ Z) {
    extern __shared__ float sm[];
    unsigned* Whi = (unsigned*)sm;            // WFRAG_N u32
    unsigned* Wlo = Whi + WFRAG_N;            // WFRAG_N u32
    float* bs = (float*)(Wlo + WFRAG_N);      // 128
    float* xs = bs + CH;                      // 128*132

    stage_wfrag_hl(Whi, Wlo, W, threadIdx.x, THREADS);
    if (threadIdx.x < CH) bs[threadIdx.x] = B[threadIdx.x];
    __syncthreads();

    int warp = threadIdx.x >> 5, lane = threadIdx.x & 31;
    int c0 = lane * 4;

    for (int tb = blockIdx.x; tb * TILE < NN; tb += gridDim.x) {
        int tile = tb * TILE;
#pragma unroll
        for (int r = 0; r < 8; r++) {
            int lr = warp * 8 + r;
            int m = tile + lr;
            float4 v = make_float4(0.f, 0.f, 0.f, 0.f);
            if (m < NN) v = *(const float4*)(X + (size_t)m * CH + c0);
            *(float4*)&xs[lr * XST + c0] = v;
        }
        PAIR_BAR(warp >> 1);
        mma_strip<false>(Whi, Wlo, xs, bs, Z, tile, warp, lane, nullptr, nullptr);
        PAIR_BAR(warp >> 1);
    }
}

// ------- fused: aggregate (gather) + tensor GEMM + BN stats -----------------
__global__ void __launch_bounds__(THREADS, 1)
k_aggemm(const float* __restrict__ W, const float* __restrict__ B,
         const float* __restrict__ We, const float* __restrict__ be,
         float* __restrict__ Z, float* __restrict__ stats) {
    extern __shared__ float sm[];
    unsigned* Whi = (unsigned*)sm;            // WFRAG_N u32
    unsigned* Wlo = Whi + WFRAG_N;            // WFRAG_N u32
    float* bs  = (float*)(Wlo + WFRAG_N);     // 128
    float* Wes = bs + CH;                     // 16*128
    float* bes = Wes + EF * CH;               // 128
    float* xs  = bes + CH;                    // 128*132

    stage_wfrag_hl(Whi, Wlo, W, threadIdx.x, THREADS);
    for (int i = threadIdx.x; i < EF * CH; i += THREADS) Wes[i] = We[i];
    if (threadIdx.x < CH) { bs[threadIdx.x] = B[threadIdx.x]; bes[threadIdx.x] = be[threadIdx.x]; }
    __syncthreads();

    int warp = threadIdx.x >> 5, lane = threadIdx.x & 31;
    int c0 = lane * 4;

    float cs[16], cq[16];
#pragma unroll
    for (int j = 0; j < 16; j++) { cs[j] = 0.f; cq[j] = 0.f; }

    for (int tb = blockIdx.x; tb * TILE < NN; tb += gridDim.x) {
        int tile = tb * TILE;
        // ---- gather: warp builds its 8 rows (pair = full 16-row strip) ----
#pragma unroll 1
        for (int r = 0; r < 8; r++) {
            int lr = warp * 8 + r;
            int n = tile + lr;
            float4 acc = make_float4(0.f, 0.f, 0.f, 0.f);
            float4 ac2 = make_float4(0.f, 0.f, 0.f, 0.f);
            if (n < NN) {
                acc = *(const float4*)(g_h + (size_t)n * CH + c0);
                int beg = g_rowptr[n], end = g_rowptr[n + 1];
                float dg = (float)(end - beg);
                float4 b4 = *(const float4*)&bes[c0];
                acc.x += dg * b4.x; acc.y += dg * b4.y;
                acc.z += dg * b4.z; acc.w += dg * b4.w;
#pragma unroll
                for (int k = 0; k < EF; k++) {
                    float ev = g_ea[(size_t)n * EF + k];
                    float4 w = *(const float4*)&Wes[k * CH + c0];
                    acc.x += ev * w.x; acc.y += ev * w.y;
                    acc.z += ev * w.z; acc.w += ev * w.w;
                }
                int e = beg;
                for (; e + 4 <= end; e += 4) {
                    int s0 = g_col[e], s1 = g_col[e + 1];
                    int s2 = g_col[e + 2], s3 = g_col[e + 3];
                    float4 v0 = *(const float4*)(g_h + (size_t)s0 * CH + c0);
                    float4 v1 = *(const float4*)(g_h + (size_t)s1 * CH + c0);
                    float4 v2 = *(const float4*)(g_h + (size_t)s2 * CH + c0);
                    float4 v3 = *(const float4*)(g_h + (size_t)s3 * CH + c0);
                    acc.x += v0.x + v1.x; ac2.x += v2.x + v3.x;
                    acc.y += v0.y + v1.y; ac2.y += v2.y + v3.y;
                    acc.z += v0.z + v1.z; ac2.z += v2.z + v3.z;
                    acc.w += v0.w + v1.w; ac2.w += v2.w + v3.w;
                }
                for (; e < end; e++) {
                    int s = g_col[e];
                    float4 v = *(const float4*)(g_h + (size_t)s * CH + c0);
                    ac2.x += v.x; ac2.y += v.y; ac2.z += v.z; ac2.w += v.w;
                }
                acc.x += ac2.x; acc.y += ac2.y; acc.z += ac2.z; acc.w += ac2.w;
            }
            *(float4*)&xs[lr * XST + c0] = acc;
        }
        PAIR_BAR(warp >> 1);
        mma_strip<true>(Whi, Wlo, xs, bs, Z, tile, warp, lane, cs, cq);
        PAIR_BAR(warp >> 1);
    }

    // ---- stats flush: reuse xs as 256-slot scratch ----
    __syncthreads();
    if (threadIdx.x < 256) xs[threadIdx.x] = 0.f;
    __syncthreads();
    {
        int nh = warp & 1, t = lane & 3;
#pragma unroll
        for (int j = 0; j < 8; j++) {
            int col = (nh * 8 + j) * 8 + 2 * t;
            atomicAdd(&xs[col], cs[2 * j]);
            atomicAdd(&xs[col + 1], cs[2 * j + 1]);
            atomicAdd(&xs[CH + col], cq[2 * j]);
            atomicAdd(&xs[CH + col + 1], cq[2 * j + 1]);
        }
    }
    __syncthreads();
    if (threadIdx.x < 256) atomicAdd(&stats[threadIdx.x], xs[threadIdx.x]);
}

// --- BN(from stats) + relu + residual + segmented pool, block per graph ----
__global__ void k_poolbn(const float* __restrict__ stats,
                         const float* __restrict__ gamma,
                         const float* __restrict__ beta,
                         const int* __restrict__ batch,
                         float* __restrict__ pooled) {
    __shared__ int s_lo, s_hi;
    int g = blockIdx.x, c = threadIdx.x;

    float mu = stats[c] * (1.0f / NN);
    float var = stats[CH + c] * (1.0f / NN) - mu * mu;
    float sc = gamma[c] * rsqrtf(var + BN_EPS);
    float sh = beta[c] - mu * sc;

    if (c < 2) {
        int tgt = g + c;
        int lo = 0, hi = NN;
        while (lo < hi) {
            int mid = (lo + hi) >> 1;
            if (batch[mid] < tgt) lo = mid + 1; else hi = mid;
        }
        if (c == 0) s_lo = lo; else s_hi = lo;
    }
    __syncthreads();
    int gs = s_lo, ge = s_hi;

    float a0 = 0.f, a1 = 0.f;
    int n = gs;
    for (; n + 2 <= ge; n += 2) {
        float z0 = g_z[(size_t)n * CH + c];
        float h0 = g_h[(size_t)n * CH + c];
        float z1 = g_z[(size_t)(n + 1) * CH + c];
        float h1 = g_h[(size_t)(n + 1) * CH + c];
        float o0 = fmaxf(fmaf(z0, sc, sh), 0.f) + h0;
        float o1 = fmaxf(fmaf(z1, sc, sh), 0.f) + h1;
        g_h[(size_t)n * CH + c] = o0;
        g_h[(size_t)(n + 1) * CH + c] = o1;
        a0 += o0; a1 += o1;
    }
    if (n < ge) {
        float z0 = g_z[(size_t)n * CH + c];
        float h0 = g_h[(size_t)n * CH + c];
        float o0 = fmaxf(fmaf(z0, sc, sh), 0.f) + h0;
        g_h[(size_t)n * CH + c] = o0;
        a0 += o0;
    }
    pooled[(size_t)g * CH + c] = a0 + a1;
}

// ------------------------- pool layer 0 (block per graph) ------------------
__global__ void k_pool0(const int* __restrict__ batch, float* __restrict__ pooled) {
    __shared__ int s_lo, s_hi;
    int g = blockIdx.x, c = threadIdx.x;
    if (c < 2) {
        int tgt = g + c;
        int lo = 0, hi = NN;
        while (lo < hi) {
            int mid = (lo + hi) >> 1;
            if (batch[mid] < tgt) lo = mid + 1; else hi = mid;
        }
        if (c == 0) s_lo = lo; else s_hi = lo;
    }
    __syncthreads();
    int gs = s_lo, ge = s_hi;

    float a0 = 0.f, a1 = 0.f, a2 = 0.f, a3 = 0.f;
    int n = gs;
    for (; n + 4 <= ge; n += 4) {
        a0 += g_h[(size_t)n * CH + c];
        a1 += g_h[(size_t)(n + 1) * CH + c];
        a2 += g_h[(size_t)(n + 2) * CH + c];
        a3 += g_h[(size_t)(n + 3) * CH + c];
    }
    for (; n < ge; n++) a0 += g_h[(size_t)n * CH + c];
    pooled[(size_t)g * CH + c] = (a0 + a1) + (a2 + a3);
}

// ------------------------- JK heads ----------------------------------------
__global__ void k_jk(const float* __restrict__ jkW, const float* __restrict__ jkb,
                     float* __restrict__ out) {
    int idx = blockIdx.x * blockDim.x + threadIdx.x;
    if (idx >= GG * NC) return;
    int g = idx / NC, c = idx % NC;
    float acc = 0.f;
#pragma unroll
    for (int l = 0; l < NL + 1; l++) {
        acc += jkb[l * NC + c];
        const float* p = g_pooled + ((size_t)l * GG + g) * CH;
        const float* w = jkW + l * CH * NC + c;
        float a = 0.f;
#pragma unroll 8
        for (int k = 0; k < CH; k++) a += p[k] * w[k * NC];
        acc += a;
    }
    out[idx] = acc;
}

// ------------------------- host launch -------------------------------------
extern "C" void kernel_launch(void* const* d_in, const int* in_sizes, int n_in,
                              void* d_out, int out_size) {
    (void)in_sizes; (void)n_in; (void)out_size;
    const float* h_in   = (const float*)d_in[0];
    const float* eattr  = (const float*)d_in[1];
    const int*   ei     = (const int*)d_in[2];
    const int*   batch  = (const int*)d_in[5];
    const float* embW   = (const float*)d_in[6];
    const float* embB   = (const float*)d_in[7];
    const float* convW  = (const float*)d_in[8];
    const float* convB  = (const float*)d_in[9];
    const float* convWe = (const float*)d_in[10];
    const float* convBe = (const float*)d_in[11];
    const float* gamma  = (const float*)d_in[12];
    const float* beta   = (const float*)d_in[13];
    const float* jkW    = (const float*)d_in[14];
    const float* jkb    = (const float*)d_in[15];
    float* out = (float*)d_out;

    void *p_deg, *p_pooled, *p_stats, *p_h, *p_z;
    cudaGetSymbolAddress(&p_deg, g_deg);
    cudaGetSymbolAddress(&p_pooled, g_pooled);
    cudaGetSymbolAddress(&p_stats, g_stats);
    cudaGetSymbolAddress(&p_h, g_h);
    cudaGetSymbolAddress(&p_z, g_z);

    const int smem_g = (2 * WFRAG_N + CH + TILE * XST) * (int)sizeof(float);
    const int smem_a = (2 * WFRAG_N + CH + EF * CH + CH + TILE * XST) * (int)sizeof(float);
    cudaFuncSetAttribute(k_gemm, cudaFuncAttributeMaxDynamicSharedMemorySize, smem_g);
    cudaFuncSetAttribute(k_aggemm, cudaFuncAttributeMaxDynamicSharedMemorySize, smem_a);

    cudaMemsetAsync(p_deg, 0, NN * sizeof(int));
    cudaMemsetAsync(p_stats, 0, NL * 2 * CH * sizeof(float));

    const int nb = (NN + 1023) / 1024;  // 49
    k_deg<<<(EE + 255) / 256, 256>>>(ei);          // kernel 1
    k_scan1<<<nb, 1024>>>();                       // kernel 2
    k_scan3<<<nb, 1024>>>(nb);                     // kernel 3
    k_gemm<<<148, THREADS, smem_g>>>(h_in, embW, embB, (float*)p_h);  // kernel 4 (profiled)
    k_fill<<<(EE + 255) / 256, 256>>>(ei);
    k_ea<<<(NN * 16 + 255) / 256, 256>>>(eattr);
    k_pool0<<<GG, CH>>>(batch, (float*)p_pooled);

    for (int l = 0; l < NL; l++) {
        k_aggemm<<<148, THREADS, smem_a>>>(convW + (size_t)l * CH * CH,
                                           convB + (size_t)l * CH,
                                           convWe + (size_t)l * EF * CH,
                                           convBe + (size_t)l * CH,
                                           (float*)p_z,
                                           (float*)p_stats + (size_t)l * 2 * CH);
        k_poolbn<<<GG, CH>>>((const float*)p_stats + (size_t)l * 2 * CH,
                             gamma + (size_t)l * CH, beta + (size_t)l * CH,
                             batch, (float*)p_pooled + (size_t)(l + 1) * GG * CH);
    }

    k_jk<<<(GG * NC + 255) / 256, 256>>>(jkW, jkb, out);
}

// round 13
// speedup vs baseline: 1.5863x; 1.5863x over previous
#include <cuda_runtime.h>

#define NN 50000
#define EE 800000
#define GG 500
#define CH 128
#define EF 16
#define NL 4
#define NC 10
#define BN_EPS 1e-5f

// packed-f32x2 FMA (Blackwell): d.{lo,hi} += a.{lo,hi} * b.{lo,hi}
#define FMA2(d, a, b) asm("fma.rn.f32x2 %0, %1, %2, %0;" : "+l"(d) : "l"(a), "l"(b))
#define PACK_DUP(d, x) asm("mov.b64 %0, {%1, %1};" : "=l"(d) : "r"(__float_as_uint(x)))

#define TR 8                // rows per warp
#define NWARP 8             // warps per block
#define TILE (NWARP * TR)   // 64 rows per block

// ------------------------- scratch (device globals, no allocation) ---------
__device__ __align__(16) float g_h[NN * CH];
__device__ __align__(16) float g_z[NN * CH];
__device__ __align__(16) float g_ea[NN * EF];
__device__ int   g_deg[NN];
__device__ int   g_rowptr[NN + 1];
__device__ int   g_cursor[NN];
__device__ int   g_col[EE];   // CSR: src sorted by dst
__device__ int   g_eid[EE];   // CSR: edge id sorted by dst
__device__ int   g_bsum[64];
__device__ __align__(16) float g_stats[NL * 2 * CH];
__device__ __align__(16) float g_pooled[(NL + 1) * GG * CH];

// ------------------------- degree count ------------------------------------
__global__ void k_deg(const int* __restrict__ ei) {
    int e = blockIdx.x * blockDim.x + threadIdx.x;
    if (e >= EE) return;
    atomicAdd(&g_deg[ei[EE + e]], 1);
}

// ------------------------- scan pass 1: per-block sums ---------------------
__global__ void k_scan1() {
    __shared__ int s[1024];
    int i = blockIdx.x * 1024 + threadIdx.x;
    s[threadIdx.x] = (i < NN) ? g_deg[i] : 0;
    __syncthreads();
    for (int off = 512; off > 0; off >>= 1) {
        if (threadIdx.x < off) s[threadIdx.x] += s[threadIdx.x + off];
        __syncthreads();
    }
    if (threadIdx.x == 0) g_bsum[blockIdx.x] = s[0];
}

// ------------- scan pass 2: per-block base + local scan --------------------
__global__ void k_scan3(int nb) {
    __shared__ int s[1024];
    __shared__ int base;
    if (threadIdx.x == 0) {
        int run = 0;
        for (int b = 0; b < blockIdx.x; b++) run += g_bsum[b];
        base = run;
        if (blockIdx.x == 0) g_rowptr[NN] = EE;
    }
    int i = blockIdx.x * 1024 + threadIdx.x;
    int v = (i < NN) ? g_deg[i] : 0;
    s[threadIdx.x] = v;
    __syncthreads();
    for (int off = 1; off < 1024; off <<= 1) {
        int t = (threadIdx.x >= off) ? s[threadIdx.x - off] : 0;
        __syncthreads();
        s[threadIdx.x] += t;
        __syncthreads();
    }
    if (i < NN) {
        int r = s[threadIdx.x] - v + base;
        g_rowptr[i] = r;
        g_cursor[i] = r;
    }
}

// ------------------------- CSR fill ----------------------------------------
__global__ void k_fill(const int* __restrict__ ei) {
    int e = blockIdx.x * blockDim.x + threadIdx.x;
    if (e >= EE) return;
    int d = ei[EE + e];
    int pos = atomicAdd(&g_cursor[d], 1);
    g_col[pos] = ei[e];
    g_eid[pos] = e;
}

// ------------------------- ea = segment_sum(edge_attr, dst) ----------------
__global__ void k_ea(const float* __restrict__ eattr) {
    int idx = blockIdx.x * blockDim.x + threadIdx.x;
    int n = idx >> 4;
    if (n >= NN) return;
    int k = idx & 15;
    int beg = g_rowptr[n], end = g_rowptr[n + 1];
    float a0 = 0.f, a1 = 0.f;
    int e = beg;
    for (; e + 2 <= end; e += 2) {
        int i0 = g_eid[e], i1 = g_eid[e + 1];
        a0 += eattr[(size_t)i0 * EF + k];
        a1 += eattr[(size_t)i1 * EF + k];
    }
    if (e < end) a0 += eattr[(size_t)g_eid[e] * EF + k];
    g_ea[(size_t)n * EF + k] = a0 + a1;
}

// ===================== GEMM core: 8 rows/warp, 4 cols/lane ==================
// Warp-private xs slice: no cross-warp dependency -> caller uses __syncwarp.
template <bool STATS>
__device__ __forceinline__ void gemm_tile8(
    const float* __restrict__ Ws, const float* __restrict__ xs,
    unsigned long long bias0, unsigned long long bias1,
    int tile, int r0, int c0, float* __restrict__ Z,
    float* cs, float* cq) {

    unsigned long long acc[TR][2];
#pragma unroll
    for (int r = 0; r < TR; r++) { acc[r][0] = bias0; acc[r][1] = bias1; }

#pragma unroll 2
    for (int k = 0; k < CH; k += 4) {
        float4 xv[TR];
#pragma unroll
        for (int r = 0; r < TR; r++) xv[r] = *(const float4*)&xs[(r0 + r) * CH + k];
#pragma unroll
        for (int kk = 0; kk < 4; kk++) {
            ulonglong2 w2 = *(const ulonglong2*)&Ws[(k + kk) * CH + c0];
#pragma unroll
            for (int r = 0; r < TR; r++) {
                float xr = (kk == 0) ? xv[r].x : (kk == 1) ? xv[r].y
                         : (kk == 2) ? xv[r].z : xv[r].w;
                unsigned long long xp;
                PACK_DUP(xp, xr);
                FMA2(acc[r][0], xp, w2.x);
                FMA2(acc[r][1], xp, w2.y);
            }
        }
    }

#pragma unroll
    for (int r = 0; r < TR; r++) {
        int m = tile + r0 + r;
        if (m < NN) {
            ulonglong2 o;
            o.x = acc[r][0]; o.y = acc[r][1];
            *(ulonglong2*)(Z + (size_t)m * CH + c0) = o;
            if (STATS) {
                float a0 = __uint_as_float((unsigned)acc[r][0]);
                float a1 = __uint_as_float((unsigned)(acc[r][0] >> 32));
                float a2 = __uint_as_float((unsigned)acc[r][1]);
                float a3 = __uint_as_float((unsigned)(acc[r][1] >> 32));
                cs[0] += a0; cq[0] += a0 * a0;
                cs[1] += a1; cq[1] += a1 * a1;
                cs[2] += a2; cq[2] += a2 * a2;
                cs[3] += a3; cq[3] += a3 * a3;
            }
        }
    }
}

__device__ __forceinline__ void stats_flush(float* sr, int c0, int tid,
                                            const float* cs, const float* cq,
                                            float* __restrict__ stats) {
    sr[tid] = 0.f;
    __syncthreads();
#pragma unroll
    for (int j = 0; j < 4; j++) {
        atomicAdd(&sr[c0 + j], cs[j]);
        atomicAdd(&sr[CH + c0 + j], cq[j]);
    }
    __syncthreads();
    atomicAdd(&stats[tid], sr[tid]);
}

// ------------------------- plain GEMM (embedding) ---------------------------
__global__ void __launch_bounds__(256, 2)
k_gemm(const float* __restrict__ X, const float* __restrict__ W,
       const float* __restrict__ B, float* __restrict__ Z) {
    extern __shared__ float sm[];
    float* Ws = sm;                  // 128*128
    float* bs = Ws + CH * CH;        // 128
    float* xs = bs + CH;             // TILE*128

    for (int i = threadIdx.x; i < CH * CH; i += 256) Ws[i] = W[i];
    if (threadIdx.x < CH) bs[threadIdx.x] = B[threadIdx.x];
    __syncthreads();

    int warp = threadIdx.x >> 5, lane = threadIdx.x & 31;
    int c0 = lane * 4, r0 = warp * TR;
    unsigned long long bias0 = *(const unsigned long long*)&bs[c0];
    unsigned long long bias1 = *(const unsigned long long*)&bs[c0 + 2];
    float cs[4], cq[4];

    for (int tile = blockIdx.x * TILE; tile < NN; tile += gridDim.x * TILE) {
#pragma unroll
        for (int r = 0; r < TR; r++) {
            int m = tile + r0 + r;
            float4 v = make_float4(0.f, 0.f, 0.f, 0.f);
            if (m < NN) v = *(const float4*)(X + (size_t)m * CH + c0);
            *(float4*)&xs[(r0 + r) * CH + c0] = v;
        }
        __syncwarp();   // warp-private slice: intra-warp ordering only
        gemm_tile8<false>(Ws, xs, bias0, bias1, tile, r0, c0, Z, cs, cq);
        __syncwarp();   // WAR: all lanes done reading before next overwrite
    }
}

// ------------- fused: aggregate (gather) + GEMM + BN stats ------------------
__global__ void __launch_bounds__(256, 2)
k_aggemm(const float* __restrict__ W, const float* __restrict__ B,
         const float* __restrict__ We, const float* __restrict__ be,
         float* __restrict__ Z, float* __restrict__ stats) {
    extern __shared__ float sm[];
    float* Ws  = sm;                  // 128*128
    float* bs  = Ws + CH * CH;        // 128
    float* Wes = bs + CH;             // 16*128
    float* bes = Wes + EF * CH;       // 128
    float* xs  = bes + CH;            // TILE*128

    for (int i = threadIdx.x; i < CH * CH; i += 256) Ws[i] = W[i];
    for (int i = threadIdx.x; i < EF * CH; i += 256) Wes[i] = We[i];
    if (threadIdx.x < CH) { bs[threadIdx.x] = B[threadIdx.x]; bes[threadIdx.x] = be[threadIdx.x]; }
    __syncthreads();

    int warp = threadIdx.x >> 5, lane = threadIdx.x & 31;
    int c0 = lane * 4, r0 = warp * TR;
    unsigned long long bias0 = *(const unsigned long long*)&bs[c0];
    unsigned long long bias1 = *(const unsigned long long*)&bs[c0 + 2];

    float cs[4] = {0.f, 0.f, 0.f, 0.f};
    float cq[4] = {0.f, 0.f, 0.f, 0.f};

    for (int tile = blockIdx.x * TILE; tile < NN; tile += gridDim.x * TILE) {
        // ---- gather/aggregate phase (warp-private rows) ----
#pragma unroll 1
        for (int r = 0; r < TR; r++) {
            int n = tile + r0 + r;
            float4 acc = make_float4(0.f, 0.f, 0.f, 0.f);
            float4 ac2 = make_float4(0.f, 0.f, 0.f, 0.f);
            if (n < NN) {
                acc = *(const float4*)(g_h + (size_t)n * CH + c0);
                int beg = g_rowptr[n], end = g_rowptr[n + 1];
                float dg = (float)(end - beg);
                float4 b4 = *(const float4*)&bes[c0];
                acc.x += dg * b4.x; acc.y += dg * b4.y;
                acc.z += dg * b4.z; acc.w += dg * b4.w;
#pragma unroll
                for (int k = 0; k < EF; k++) {
                    float ev = g_ea[(size_t)n * EF + k];
                    float4 w = *(const float4*)&Wes[k * CH + c0];
                    acc.x += ev * w.x; acc.y += ev * w.y;
                    acc.z += ev * w.z; acc.w += ev * w.w;
                }
                int e = beg;
                for (; e + 4 <= end; e += 4) {
                    int s0 = g_col[e], s1 = g_col[e + 1];
                    int s2 = g_col[e + 2], s3 = g_col[e + 3];
                    float4 v0 = *(const float4*)(g_h + (size_t)s0 * CH + c0);
                    float4 v1 = *(const float4*)(g_h + (size_t)s1 * CH + c0);
                    float4 v2 = *(const float4*)(g_h + (size_t)s2 * CH + c0);
                    float4 v3 = *(const float4*)(g_h + (size_t)s3 * CH + c0);
                    acc.x += v0.x + v1.x; ac2.x += v2.x + v3.x;
                    acc.y += v0.y + v1.y; ac2.y += v2.y + v3.y;
                    acc.z += v0.z + v1.z; ac2.z += v2.z + v3.z;
                    acc.w += v0.w + v1.w; ac2.w += v2.w + v3.w;
                }
                for (; e < end; e++) {
                    int s = g_col[e];
                    float4 v = *(const float4*)(g_h + (size_t)s * CH + c0);
                    ac2.x += v.x; ac2.y += v.y; ac2.z += v.z; ac2.w += v.w;
                }
                acc.x += ac2.x; acc.y += ac2.y; acc.z += ac2.z; acc.w += ac2.w;
            }
            *(float4*)&xs[(r0 + r) * CH + c0] = acc;
        }
        __syncwarp();   // warp-private slice: intra-warp ordering only
        gemm_tile8<true>(Ws, xs, bias0, bias1, tile, r0, c0, Z, cs, cq);
        __syncwarp();   // WAR before next gather overwrites the slice
    }

    __syncthreads();    // all warps done before reusing xs as scratch
    stats_flush(xs, c0, threadIdx.x, cs, cq, stats);
}

// --- BN(from stats) + relu + residual + segmented pool, block per graph ----
__global__ void k_poolbn(const float* __restrict__ stats,
                         const float* __restrict__ gamma,
                         const float* __restrict__ beta,
                         const int* __restrict__ batch,
                         float* __restrict__ pooled) {
    __shared__ int s_lo, s_hi;
    int g = blockIdx.x, c = threadIdx.x;

    float mu = stats[c] * (1.0f / NN);
    float var = stats[CH + c] * (1.0f / NN) - mu * mu;
    float sc = gamma[c] * rsqrtf(var + BN_EPS);
    float sh = beta[c] - mu * sc;

    if (c < 2) {
        int tgt = g + c;
        int lo = 0, hi = NN;
        while (lo < hi) {
            int mid = (lo + hi) >> 1;
            if (batch[mid] < tgt) lo = mid + 1; else hi = mid;
        }
        if (c == 0) s_lo = lo; else s_hi = lo;
    }
    __syncthreads();
    int gs = s_lo, ge = s_hi;

    float a0 = 0.f, a1 = 0.f;
    int n = gs;
    for (; n + 2 <= ge; n += 2) {
        float z0 = g_z[(size_t)n * CH + c];
        float h0 = g_h[(size_t)n * CH + c];
        float z1 = g_z[(size_t)(n + 1) * CH + c];
        float h1 = g_h[(size_t)(n + 1) * CH + c];
        float o0 = fmaxf(fmaf(z0, sc, sh), 0.f) + h0;
        float o1 = fmaxf(fmaf(z1, sc, sh), 0.f) + h1;
        g_h[(size_t)n * CH + c] = o0;
        g_h[(size_t)(n + 1) * CH + c] = o1;
        a0 += o0; a1 += o1;
    }
    if (n < ge) {
        float z0 = g_z[(size_t)n * CH + c];
        float h0 = g_h[(size_t)n * CH + c];
        float o0 = fmaxf(fmaf(z0, sc, sh), 0.f) + h0;
        g_h[(size_t)n * CH + c] = o0;
        a0 += o0;
    }
    pooled[(size_t)g * CH + c] = a0 + a1;
}

// ------------------------- pool layer 0 (block per graph) ------------------
__global__ void k_pool0(const int* __restrict__ batch, float* __restrict__ pooled) {
    __shared__ int s_lo, s_hi;
    int g = blockIdx.x, c = threadIdx.x;
    if (c < 2) {
        int tgt = g + c;
        int lo = 0, hi = NN;
        while (lo < hi) {
            int mid = (lo + hi) >> 1;
            if (batch[mid] < tgt) lo = mid + 1; else hi = mid;
        }
        if (c == 0) s_lo = lo; else s_hi = lo;
    }
    __syncthreads();
    int gs = s_lo, ge = s_hi;

    float a0 = 0.f, a1 = 0.f, a2 = 0.f, a3 = 0.f;
    int n = gs;
    for (; n + 4 <= ge; n += 4) {
        a0 += g_h[(size_t)n * CH + c];
        a1 += g_h[(size_t)(n + 1) * CH + c];
        a2 += g_h[(size_t)(n + 2) * CH + c];
        a3 += g_h[(size_t)(n + 3) * CH + c];
    }
    for (; n < ge; n++) a0 += g_h[(size_t)n * CH + c];
    pooled[(size_t)g * CH + c] = (a0 + a1) + (a2 + a3);
}

// ------------------------- JK heads ----------------------------------------
__global__ void k_jk(const float* __restrict__ jkW, const float* __restrict__ jkb,
                     float* __restrict__ out) {
    int idx = blockIdx.x * blockDim.x + threadIdx.x;
    if (idx >= GG * NC) return;
    int g = idx / NC, c = idx % NC;
    float acc = 0.f;
#pragma unroll
    for (int l = 0; l < NL + 1; l++) {
        acc += jkb[l * NC + c];
        const float* p = g_pooled + ((size_t)l * GG + g) * CH;
        const float* w = jkW + l * CH * NC + c;
        float a = 0.f;
#pragma unroll 8
        for (int k = 0; k < CH; k++) a += p[k] * w[k * NC];
        acc += a;
    }
    out[idx] = acc;
}

// ------------------------- host launch -------------------------------------
extern "C" void kernel_launch(void* const* d_in, const int* in_sizes, int n_in,
                              void* d_out, int out_size) {
    (void)in_sizes; (void)n_in; (void)out_size;
    const float* h_in   = (const float*)d_in[0];
    const float* eattr  = (const float*)d_in[1];
    const int*   ei     = (const int*)d_in[2];
    const int*   batch  = (const int*)d_in[5];
    const float* embW   = (const float*)d_in[6];
    const float* embB   = (const float*)d_in[7];
    const float* convW  = (const float*)d_in[8];
    const float* convB  = (const float*)d_in[9];
    const float* convWe = (const float*)d_in[10];
    const float* convBe = (const float*)d_in[11];
    const float* gamma  = (const float*)d_in[12];
    const float* beta   = (const float*)d_in[13];
    const float* jkW    = (const float*)d_in[14];
    const float* jkb    = (const float*)d_in[15];
    float* out = (float*)d_out;

    void *p_deg, *p_pooled, *p_stats, *p_h, *p_z;
    cudaGetSymbolAddress(&p_deg, g_deg);
    cudaGetSymbolAddress(&p_pooled, g_pooled);
    cudaGetSymbolAddress(&p_stats, g_stats);
    cudaGetSymbolAddress(&p_h, g_h);
    cudaGetSymbolAddress(&p_z, g_z);

    const int smem_g = (CH * CH + CH + TILE * CH) * (int)sizeof(float);
    const int smem_a = (CH * CH + CH + EF * CH + CH + TILE * CH) * (int)sizeof(float);
    cudaFuncSetAttribute(k_gemm, cudaFuncAttributeMaxDynamicSharedMemorySize, smem_g);
    cudaFuncSetAttribute(k_aggemm, cudaFuncAttributeMaxDynamicSharedMemorySize, smem_a);

    // Fork a side stream for the CSR-build chain; it runs concurrently with
    // the embedding GEMM + layer-0 pool on the main stream. kernel_launch is
    // only invoked a handful of times (correctness + capture), so creating
    // the stream/events per call is cheap and keeps the captured work
    // identical on every call.
    cudaStream_t s2;
    cudaEvent_t ev_fork, ev_join;
    cudaStreamCreateWithFlags(&s2, cudaStreamNonBlocking);
    cudaEventCreateWithFlags(&ev_fork, cudaEventDisableTiming);
    cudaEventCreateWithFlags(&ev_join, cudaEventDisableTiming);

    cudaEventRecord(ev_fork, 0);
    cudaStreamWaitEvent(s2, ev_fork, 0);

    // ---- branch A (s2): CSR build ----
    const int nb = (NN + 1023) / 1024;  // 49
    cudaMemsetAsync(p_deg, 0, NN * sizeof(int), s2);
    k_deg<<<(EE + 255) / 256, 256, 0, s2>>>(ei);
    k_scan1<<<nb, 1024, 0, s2>>>();
    k_scan3<<<nb, 1024, 0, s2>>>(nb);
    k_fill<<<(EE + 255) / 256, 256, 0, s2>>>(ei);
    k_ea<<<(NN * 16 + 255) / 256, 256, 0, s2>>>(eattr);

    // ---- branch B (main): embedding GEMM + layer-0 pool + stats clear ----
    cudaMemsetAsync(p_stats, 0, NL * 2 * CH * sizeof(float));
    k_gemm<<<296, 256, smem_g>>>(h_in, embW, embB, (float*)p_h);
    k_pool0<<<GG, CH>>>(batch, (float*)p_pooled);

    // ---- join ----
    cudaEventRecord(ev_join, s2);
    cudaStreamWaitEvent(0, ev_join, 0);

    // conv layers (sequential dependency chain)
    for (int l = 0; l < NL; l++) {
        k_aggemm<<<296, 256, smem_a>>>(convW + (size_t)l * CH * CH,
                                       convB + (size_t)l * CH,
                                       convWe + (size_t)l * EF * CH,
                                       convBe + (size_t)l * CH,
                                       (float*)p_z,
                                       (float*)p_stats + (size_t)l * 2 * CH);
        k_poolbn<<<GG, CH>>>((const float*)p_stats + (size_t)l * 2 * CH,
                             gamma + (size_t)l * CH, beta + (size_t)l * CH,
                             batch, (float*)p_pooled + (size_t)(l + 1) * GG * CH);
    }

    k_jk<<<(GG * NC + 255) / 256, 256>>>(jkW, jkb, out);
}

// round 14
// speedup vs baseline: 1.6053x; 1.0120x over previous
#include <cuda_runtime.h>

#define NN 50000
#define EE 800000
#define GG 500
#define CH 128
#define EF 16
#define NL 4
#define NC 10
#define BN_EPS 1e-5f

// packed-f32x2 FMA (Blackwell): d.{lo,hi} += a.{lo,hi} * b.{lo,hi}
#define FMA2(d, a, b) asm("fma.rn.f32x2 %0, %1, %2, %0;" : "+l"(d) : "l"(a), "l"(b))
#define PACK_DUP(d, x) asm("mov.b64 %0, {%1, %1};" : "=l"(d) : "r"(__float_as_uint(x)))

#define TR 8                // rows per warp
#define NWARP 8             // warps per block
#define TILE (NWARP * TR)   // 64 rows per block

// ------------------------- scratch (device globals, no allocation) ---------
__device__ __align__(16) float g_h[NN * CH];
__device__ __align__(16) float g_z[NN * CH];
__device__ __align__(16) float g_ea[NN * EF];
__device__ int   g_deg[NN];
__device__ int   g_rowptr[NN + 1];
__device__ int   g_cursor[NN];
__device__ int   g_col[EE];   // CSR: src sorted by dst
__device__ int   g_eid[EE];   // CSR: edge id sorted by dst
__device__ int   g_bsum[64];
__device__ __align__(16) float g_stats[NL * 2 * CH];
__device__ __align__(16) float g_pooled[(NL + 1) * GG * CH];

// ------------------------- degree count ------------------------------------
__global__ void k_deg(const int* __restrict__ ei) {
    int e = blockIdx.x * blockDim.x + threadIdx.x;
    if (e >= EE) return;
    atomicAdd(&g_deg[ei[EE + e]], 1);
}

// ------------------------- scan pass 1: per-block sums ---------------------
__global__ void k_scan1() {
    __shared__ int s[1024];
    int i = blockIdx.x * 1024 + threadIdx.x;
    s[threadIdx.x] = (i < NN) ? g_deg[i] : 0;
    __syncthreads();
    for (int off = 512; off > 0; off >>= 1) {
        if (threadIdx.x < off) s[threadIdx.x] += s[threadIdx.x + off];
        __syncthreads();
    }
    if (threadIdx.x == 0) g_bsum[blockIdx.x] = s[0];
}

// ------------- scan pass 2: per-block base + local scan --------------------
__global__ void k_scan3(int nb) {
    __shared__ int s[1024];
    __shared__ int base;
    if (threadIdx.x == 0) {
        int run = 0;
        for (int b = 0; b < blockIdx.x; b++) run += g_bsum[b];
        base = run;
        if (blockIdx.x == 0) g_rowptr[NN] = EE;
    }
    int i = blockIdx.x * 1024 + threadIdx.x;
    int v = (i < NN) ? g_deg[i] : 0;
    s[threadIdx.x] = v;
    __syncthreads();
    for (int off = 1; off < 1024; off <<= 1) {
        int t = (threadIdx.x >= off) ? s[threadIdx.x - off] : 0;
        __syncthreads();
        s[threadIdx.x] += t;
        __syncthreads();
    }
    if (i < NN) {
        int r = s[threadIdx.x] - v + base;
        g_rowptr[i] = r;
        g_cursor[i] = r;
    }
}

// ------------------------- CSR fill ----------------------------------------
__global__ void k_fill(const int* __restrict__ ei) {
    int e = blockIdx.x * blockDim.x + threadIdx.x;
    if (e >= EE) return;
    int d = ei[EE + e];
    int pos = atomicAdd(&g_cursor[d], 1);
    g_col[pos] = ei[e];
    g_eid[pos] = e;
}

// ------------------------- ea = segment_sum(edge_attr, dst) ----------------
__global__ void k_ea(const float* __restrict__ eattr) {
    int idx = blockIdx.x * blockDim.x + threadIdx.x;
    int n = idx >> 4;
    if (n >= NN) return;
    int k = idx & 15;
    int beg = g_rowptr[n], end = g_rowptr[n + 1];
    float a0 = 0.f, a1 = 0.f;
    int e = beg;
    for (; e + 2 <= end; e += 2) {
        int i0 = g_eid[e], i1 = g_eid[e + 1];
        a0 += eattr[(size_t)i0 * EF + k];
        a1 += eattr[(size_t)i1 * EF + k];
    }
    if (e < end) a0 += eattr[(size_t)g_eid[e] * EF + k];
    g_ea[(size_t)n * EF + k] = a0 + a1;
}

// ===================== GEMM core: 8 rows/warp, 4 cols/lane ==================
// Warp-private xs slice: no cross-warp dependency -> caller uses __syncwarp.
template <bool STATS>
__device__ __forceinline__ void gemm_tile8(
    const float* __restrict__ Ws, const float* __restrict__ xs,
    unsigned long long bias0, unsigned long long bias1,
    int tile, int r0, int c0, float* __restrict__ Z,
    float* cs, float* cq) {

    unsigned long long acc[TR][2];
#pragma unroll
    for (int r = 0; r < TR; r++) { acc[r][0] = bias0; acc[r][1] = bias1; }

#pragma unroll 2
    for (int k = 0; k < CH; k += 4) {
        float4 xv[TR];
#pragma unroll
        for (int r = 0; r < TR; r++) xv[r] = *(const float4*)&xs[(r0 + r) * CH + k];
#pragma unroll
        for (int kk = 0; kk < 4; kk++) {
            ulonglong2 w2 = *(const ulonglong2*)&Ws[(k + kk) * CH + c0];
#pragma unroll
            for (int r = 0; r < TR; r++) {
                float xr = (kk == 0) ? xv[r].x : (kk == 1) ? xv[r].y
                         : (kk == 2) ? xv[r].z : xv[r].w;
                unsigned long long xp;
                PACK_DUP(xp, xr);
                FMA2(acc[r][0], xp, w2.x);
                FMA2(acc[r][1], xp, w2.y);
            }
        }
    }

#pragma unroll
    for (int r = 0; r < TR; r++) {
        int m = tile + r0 + r;
        if (m < NN) {
            ulonglong2 o;
            o.x = acc[r][0]; o.y = acc[r][1];
            *(ulonglong2*)(Z + (size_t)m * CH + c0) = o;
            if (STATS) {
                float a0 = __uint_as_float((unsigned)acc[r][0]);
                float a1 = __uint_as_float((unsigned)(acc[r][0] >> 32));
                float a2 = __uint_as_float((unsigned)acc[r][1]);
                float a3 = __uint_as_float((unsigned)(acc[r][1] >> 32));
                cs[0] += a0; cq[0] += a0 * a0;
                cs[1] += a1; cq[1] += a1 * a1;
                cs[2] += a2; cq[2] += a2 * a2;
                cs[3] += a3; cq[3] += a3 * a3;
            }
        }
    }
}

__device__ __forceinline__ void stats_flush(float* sr, int c0, int tid,
                                            const float* cs, const float* cq,
                                            float* __restrict__ stats) {
    sr[tid] = 0.f;
    __syncthreads();
#pragma unroll
    for (int j = 0; j < 4; j++) {
        atomicAdd(&sr[c0 + j], cs[j]);
        atomicAdd(&sr[CH + c0 + j], cq[j]);
    }
    __syncthreads();
    atomicAdd(&stats[tid], sr[tid]);
}

// ------------------------- plain GEMM (embedding) ---------------------------
__global__ void __launch_bounds__(256, 2)
k_gemm(const float* __restrict__ X, const float* __restrict__ W,
       const float* __restrict__ B, float* __restrict__ Z) {
    extern __shared__ float sm[];
    float* Ws = sm;                  // 128*128
    float* bs = Ws + CH * CH;        // 128
    float* xs = bs + CH;             // TILE*128

    for (int i = threadIdx.x; i < CH * CH; i += 256) Ws[i] = W[i];
    if (threadIdx.x < CH) bs[threadIdx.x] = B[threadIdx.x];
    __syncthreads();

    int warp = threadIdx.x >> 5, lane = threadIdx.x & 31;
    int c0 = lane * 4, r0 = warp * TR;
    unsigned long long bias0 = *(const unsigned long long*)&bs[c0];
    unsigned long long bias1 = *(const unsigned long long*)&bs[c0 + 2];
    float cs[4], cq[4];

    for (int tile = blockIdx.x * TILE; tile < NN; tile += gridDim.x * TILE) {
#pragma unroll
        for (int r = 0; r < TR; r++) {
            int m = tile + r0 + r;
            float4 v = make_float4(0.f, 0.f, 0.f, 0.f);
            if (m < NN) v = *(const float4*)(X + (size_t)m * CH + c0);
            *(float4*)&xs[(r0 + r) * CH + c0] = v;
        }
        __syncwarp();   // warp-private slice: intra-warp ordering only
        gemm_tile8<false>(Ws, xs, bias0, bias1, tile, r0, c0, Z, cs, cq);
        __syncwarp();   // WAR: all lanes done reading before next overwrite
    }
}

// ------------- fused: aggregate (gather) + GEMM + BN stats ------------------
__global__ void __launch_bounds__(256, 2)
k_aggemm(const float* __restrict__ W, const float* __restrict__ B,
         const float* __restrict__ We, const float* __restrict__ be,
         float* __restrict__ Z, float* __restrict__ stats) {
    extern __shared__ float sm[];
    float* Ws  = sm;                  // 128*128
    float* bs  = Ws + CH * CH;        // 128
    float* Wes = bs + CH;             // 16*128
    float* bes = Wes + EF * CH;       // 128
    float* xs  = bes + CH;            // TILE*128

    for (int i = threadIdx.x; i < CH * CH; i += 256) Ws[i] = W[i];
    for (int i = threadIdx.x; i < EF * CH; i += 256) Wes[i] = We[i];
    if (threadIdx.x < CH) { bs[threadIdx.x] = B[threadIdx.x]; bes[threadIdx.x] = be[threadIdx.x]; }
    __syncthreads();

    int warp = threadIdx.x >> 5, lane = threadIdx.x & 31;
    int c0 = lane * 4, r0 = warp * TR;
    unsigned long long bias0 = *(const unsigned long long*)&bs[c0];
    unsigned long long bias1 = *(const unsigned long long*)&bs[c0 + 2];

    float cs[4] = {0.f, 0.f, 0.f, 0.f};
    float cq[4] = {0.f, 0.f, 0.f, 0.f};

    for (int tile = blockIdx.x * TILE; tile < NN; tile += gridDim.x * TILE) {
        // ---- gather/aggregate phase (warp-private rows), MLP=8 ----
#pragma unroll 1
        for (int r = 0; r < TR; r++) {
            int n = tile + r0 + r;
            float4 acc = make_float4(0.f, 0.f, 0.f, 0.f);
            float4 ac2 = make_float4(0.f, 0.f, 0.f, 0.f);
            float4 ac3 = make_float4(0.f, 0.f, 0.f, 0.f);
            float4 ac4 = make_float4(0.f, 0.f, 0.f, 0.f);
            if (n < NN) {
                acc = *(const float4*)(g_h + (size_t)n * CH + c0);
                int beg = g_rowptr[n], end = g_rowptr[n + 1];
                float dg = (float)(end - beg);
                float4 b4 = *(const float4*)&bes[c0];
                acc.x += dg * b4.x; acc.y += dg * b4.y;
                acc.z += dg * b4.z; acc.w += dg * b4.w;
#pragma unroll
                for (int k = 0; k < EF; k++) {
                    float ev = g_ea[(size_t)n * EF + k];
                    float4 w = *(const float4*)&Wes[k * CH + c0];
                    acc.x += ev * w.x; acc.y += ev * w.y;
                    acc.z += ev * w.z; acc.w += ev * w.w;
                }
                int e = beg;
                // 8 independent row loads in flight (doubles gather MLP)
                for (; e + 8 <= end; e += 8) {
                    int s0 = g_col[e],     s1 = g_col[e + 1];
                    int s2 = g_col[e + 2], s3 = g_col[e + 3];
                    int s4 = g_col[e + 4], s5 = g_col[e + 5];
                    int s6 = g_col[e + 6], s7 = g_col[e + 7];
                    float4 v0 = *(const float4*)(g_h + (size_t)s0 * CH + c0);
                    float4 v1 = *(const float4*)(g_h + (size_t)s1 * CH + c0);
                    float4 v2 = *(const float4*)(g_h + (size_t)s2 * CH + c0);
                    float4 v3 = *(const float4*)(g_h + (size_t)s3 * CH + c0);
                    float4 v4 = *(const float4*)(g_h + (size_t)s4 * CH + c0);
                    float4 v5 = *(const float4*)(g_h + (size_t)s5 * CH + c0);
                    float4 v6 = *(const float4*)(g_h + (size_t)s6 * CH + c0);
                    float4 v7 = *(const float4*)(g_h + (size_t)s7 * CH + c0);
                    acc.x += v0.x + v1.x; ac2.x += v2.x + v3.x;
                    ac3.x += v4.x + v5.x; ac4.x += v6.x + v7.x;
                    acc.y += v0.y + v1.y; ac2.y += v2.y + v3.y;
                    ac3.y += v4.y + v5.y; ac4.y += v6.y + v7.y;
                    acc.z += v0.z + v1.z; ac2.z += v2.z + v3.z;
                    ac3.z += v4.z + v5.z; ac4.z += v6.z + v7.z;
                    acc.w += v0.w + v1.w; ac2.w += v2.w + v3.w;
                    ac3.w += v4.w + v5.w; ac4.w += v6.w + v7.w;
                }
                for (; e + 2 <= end; e += 2) {
                    int s0 = g_col[e], s1 = g_col[e + 1];
                    float4 v0 = *(const float4*)(g_h + (size_t)s0 * CH + c0);
                    float4 v1 = *(const float4*)(g_h + (size_t)s1 * CH + c0);
                    ac2.x += v0.x + v1.x; ac2.y += v0.y + v1.y;
                    ac2.z += v0.z + v1.z; ac2.w += v0.w + v1.w;
                }
                if (e < end) {
                    int s = g_col[e];
                    float4 v = *(const float4*)(g_h + (size_t)s * CH + c0);
                    ac3.x += v.x; ac3.y += v.y; ac3.z += v.z; ac3.w += v.w;
                }
                acc.x += (ac2.x + ac3.x) + ac4.x;
                acc.y += (ac2.y + ac3.y) + ac4.y;
                acc.z += (ac2.z + ac3.z) + ac4.z;
                acc.w += (ac2.w + ac3.w) + ac4.w;
            }
            *(float4*)&xs[(r0 + r) * CH + c0] = acc;
        }
        __syncwarp();   // warp-private slice: intra-warp ordering only
        gemm_tile8<true>(Ws, xs, bias0, bias1, tile, r0, c0, Z, cs, cq);
        __syncwarp();   // WAR before next gather overwrites the slice
    }

    __syncthreads();    // all warps done before reusing xs as scratch
    stats_flush(xs, c0, threadIdx.x, cs, cq, stats);
}

// --- BN(from stats) + relu + residual + segmented pool, block per graph ----
__global__ void k_poolbn(const float* __restrict__ stats,
                         const float* __restrict__ gamma,
                         const float* __restrict__ beta,
                         const int* __restrict__ batch,
                         float* __restrict__ pooled) {
    __shared__ int s_lo, s_hi;
    int g = blockIdx.x, c = threadIdx.x;

    float mu = stats[c] * (1.0f / NN);
    float var = stats[CH + c] * (1.0f / NN) - mu * mu;
    float sc = gamma[c] * rsqrtf(var + BN_EPS);
    float sh = beta[c] - mu * sc;

    if (c < 2) {
        int tgt = g + c;
        int lo = 0, hi = NN;
        while (lo < hi) {
            int mid = (lo + hi) >> 1;
            if (batch[mid] < tgt) lo = mid + 1; else hi = mid;
        }
        if (c == 0) s_lo = lo; else s_hi = lo;
    }
    __syncthreads();
    int gs = s_lo, ge = s_hi;

    float a0 = 0.f, a1 = 0.f;
    int n = gs;
    for (; n + 2 <= ge; n += 2) {
        float z0 = g_z[(size_t)n * CH + c];
        float h0 = g_h[(size_t)n * CH + c];
        float z1 = g_z[(size_t)(n + 1) * CH + c];
        float h1 = g_h[(size_t)(n + 1) * CH + c];
        float o0 = fmaxf(fmaf(z0, sc, sh), 0.f) + h0;
        float o1 = fmaxf(fmaf(z1, sc, sh), 0.f) + h1;
        g_h[(size_t)n * CH + c] = o0;
        g_h[(size_t)(n + 1) * CH + c] = o1;
        a0 += o0; a1 += o1;
    }
    if (n < ge) {
        float z0 = g_z[(size_t)n * CH + c];
        float h0 = g_h[(size_t)n * CH + c];
        float o0 = fmaxf(fmaf(z0, sc, sh), 0.f) + h0;
        g_h[(size_t)n * CH + c] = o0;
        a0 += o0;
    }
    pooled[(size_t)g * CH + c] = a0 + a1;
}

// ------------------------- pool layer 0 (block per graph) ------------------
__global__ void k_pool0(const int* __restrict__ batch, float* __restrict__ pooled) {
    __shared__ int s_lo, s_hi;
    int g = blockIdx.x, c = threadIdx.x;
    if (c < 2) {
        int tgt = g + c;
        int lo = 0, hi = NN;
        while (lo < hi) {
            int mid = (lo + hi) >> 1;
            if (batch[mid] < tgt) lo = mid + 1; else hi = mid;
        }
        if (c == 0) s_lo = lo; else s_hi = lo;
    }
    __syncthreads();
    int gs = s_lo, ge = s_hi;

    float a0 = 0.f, a1 = 0.f, a2 = 0.f, a3 = 0.f;
    int n = gs;
    for (; n + 4 <= ge; n += 4) {
        a0 += g_h[(size_t)n * CH + c];
        a1 += g_h[(size_t)(n + 1) * CH + c];
        a2 += g_h[(size_t)(n + 2) * CH + c];
        a3 += g_h[(size_t)(n + 3) * CH + c];
    }
    for (; n < ge; n++) a0 += g_h[(size_t)n * CH + c];
    pooled[(size_t)g * CH + c] = (a0 + a1) + (a2 + a3);
}

// ------------------------- JK heads ----------------------------------------
__global__ void k_jk(const float* __restrict__ jkW, const float* __restrict__ jkb,
                     float* __restrict__ out) {
    int idx = blockIdx.x * blockDim.x + threadIdx.x;
    if (idx >= GG * NC) return;
    int g = idx / NC, c = idx % NC;
    float acc = 0.f;
#pragma unroll
    for (int l = 0; l < NL + 1; l++) {
        acc += jkb[l * NC + c];
        const float* p = g_pooled + ((size_t)l * GG + g) * CH;
        const float* w = jkW + l * CH * NC + c;
        float a = 0.f;
#pragma unroll 8
        for (int k = 0; k < CH; k++) a += p[k] * w[k * NC];
        acc += a;
    }
    out[idx] = acc;
}

// ------------------------- host launch -------------------------------------
extern "C" void kernel_launch(void* const* d_in, const int* in_sizes, int n_in,
                              void* d_out, int out_size) {
    (void)in_sizes; (void)n_in; (void)out_size;
    const float* h_in   = (const float*)d_in[0];
    const float* eattr  = (const float*)d_in[1];
    const int*   ei     = (const int*)d_in[2];
    const int*   batch  = (const int*)d_in[5];
    const float* embW   = (const float*)d_in[6];
    const float* embB   = (const float*)d_in[7];
    const float* convW  = (const float*)d_in[8];
    const float* convB  = (const float*)d_in[9];
    const float* convWe = (const float*)d_in[10];
    const float* convBe = (const float*)d_in[11];
    const float* gamma  = (const float*)d_in[12];
    const float* beta   = (const float*)d_in[13];
    const float* jkW    = (const float*)d_in[14];
    const float* jkb    = (const float*)d_in[15];
    float* out = (float*)d_out;

    void *p_deg, *p_pooled, *p_stats, *p_h, *p_z;
    cudaGetSymbolAddress(&p_deg, g_deg);
    cudaGetSymbolAddress(&p_pooled, g_pooled);
    cudaGetSymbolAddress(&p_stats, g_stats);
    cudaGetSymbolAddress(&p_h, g_h);
    cudaGetSymbolAddress(&p_z, g_z);

    const int smem_g = (CH * CH + CH + TILE * CH) * (int)sizeof(float);
    const int smem_a = (CH * CH + CH + EF * CH + CH + TILE * CH) * (int)sizeof(float);
    cudaFuncSetAttribute(k_gemm, cudaFuncAttributeMaxDynamicSharedMemorySize, smem_g);
    cudaFuncSetAttribute(k_aggemm, cudaFuncAttributeMaxDynamicSharedMemorySize, smem_a);

    cudaMemsetAsync(p_deg, 0, NN * sizeof(int));
    cudaMemsetAsync(p_stats, 0, NL * 2 * CH * sizeof(float));

    const int nb = (NN + 1023) / 1024;  // 49
    k_deg<<<(EE + 255) / 256, 256>>>(ei);
    k_scan1<<<nb, 1024>>>();
    k_scan3<<<nb, 1024>>>(nb);
    k_gemm<<<296, 256, smem_g>>>(h_in, embW, embB, (float*)p_h);  // profiled slot
    k_fill<<<(EE + 255) / 256, 256>>>(ei);
    k_ea<<<(NN * 16 + 255) / 256, 256>>>(eattr);
    k_pool0<<<GG, CH>>>(batch, (float*)p_pooled);

    for (int l = 0; l < NL; l++) {
        k_aggemm<<<296, 256, smem_a>>>(convW + (size_t)l * CH * CH,
                                       convB + (size_t)l * CH,
                                       convWe + (size_t)l * EF * CH,
                                       convBe + (size_t)l * CH,
                                       (float*)p_z,
                                       (float*)p_stats + (size_t)l * 2 * CH);
        k_poolbn<<<GG, CH>>>((const float*)p_stats + (size_t)l * 2 * CH,
                             gamma + (size_t)l * CH, beta + (size_t)l * CH,
                             batch, (float*)p_pooled + (size_t)(l + 1) * GG * CH);
    }

    k_jk<<<(GG * NC + 255) / 256, 256>>>(jkW, jkb, out);
}

// round 15
// speedup vs baseline: 1.6485x; 1.0269x over previous
#include <cuda_runtime.h>

#define NN 50000
#define EE 800000
#define GG 500
#define CH 128
#define EF 16
#define NL 4
#define NC 10
#define BN_EPS 1e-5f

// packed-f32x2 FMA (Blackwell): d.{lo,hi} += a.{lo,hi} * b.{lo,hi}
#define FMA2(d, a, b) asm("fma.rn.f32x2 %0, %1, %2, %0;" : "+l"(d) : "l"(a), "l"(b))
#define PACK_DUP(d, x) asm("mov.b64 %0, {%1, %1};" : "=l"(d) : "r"(__float_as_uint(x)))

#define TR 8                // rows per warp (GEMM)
#define NWARP 8             // warps per block (GEMM)
#define TILE (NWARP * TR)   // 64 rows per block

// ------------------------- scratch (device globals, no allocation) ---------
__device__ __align__(16) float g_h[NN * CH];
__device__ __align__(16) float g_x[NN * CH];
__device__ __align__(16) float g_z[NN * CH];
__device__ __align__(16) float g_ea[NN * EF];
__device__ int   g_deg[NN];
__device__ int   g_rowptr[NN + 1];
__device__ int   g_cursor[NN];
__device__ int   g_col[EE];   // CSR: src sorted by dst
__device__ int   g_eid[EE];   // CSR: edge id sorted by dst
__device__ int   g_bsum[64];
__device__ __align__(16) float g_stats[NL * 2 * CH];
__device__ __align__(16) float g_pooled[(NL + 1) * GG * CH];

// ------------------------- degree count ------------------------------------
__global__ void k_deg(const int* __restrict__ ei) {
    int e = blockIdx.x * blockDim.x + threadIdx.x;
    if (e >= EE) return;
    atomicAdd(&g_deg[ei[EE + e]], 1);
}

// ------------------------- scan pass 1: per-block sums ---------------------
__global__ void k_scan1() {
    __shared__ int s[1024];
    int i = blockIdx.x * 1024 + threadIdx.x;
    s[threadIdx.x] = (i < NN) ? g_deg[i] : 0;
    __syncthreads();
    for (int off = 512; off > 0; off >>= 1) {
        if (threadIdx.x < off) s[threadIdx.x] += s[threadIdx.x + off];
        __syncthreads();
    }
    if (threadIdx.x == 0) g_bsum[blockIdx.x] = s[0];
}

// ------------- scan pass 2: per-block base + local scan --------------------
__global__ void k_scan3(int nb) {
    __shared__ int s[1024];
    __shared__ int base;
    if (threadIdx.x == 0) {
        int run = 0;
        for (int b = 0; b < blockIdx.x; b++) run += g_bsum[b];
        base = run;
        if (blockIdx.x == 0) g_rowptr[NN] = EE;
    }
    int i = blockIdx.x * 1024 + threadIdx.x;
    int v = (i < NN) ? g_deg[i] : 0;
    s[threadIdx.x] = v;
    __syncthreads();
    for (int off = 1; off < 1024; off <<= 1) {
        int t = (threadIdx.x >= off) ? s[threadIdx.x - off] : 0;
        __syncthreads();
        s[threadIdx.x] += t;
        __syncthreads();
    }
    if (i < NN) {
        int r = s[threadIdx.x] - v + base;
        g_rowptr[i] = r;
        g_cursor[i] = r;
    }
}

// ------------------------- CSR fill ----------------------------------------
__global__ void k_fill(const int* __restrict__ ei) {
    int e = blockIdx.x * blockDim.x + threadIdx.x;
    if (e >= EE) return;
    int d = ei[EE + e];
    int pos = atomicAdd(&g_cursor[d], 1);
    g_col[pos] = ei[e];
    g_eid[pos] = e;
}

// ------------------------- ea = segment_sum(edge_attr, dst) ----------------
__global__ void k_ea(const float* __restrict__ eattr) {
    int idx = blockIdx.x * blockDim.x + threadIdx.x;
    int n = idx >> 4;
    if (n >= NN) return;
    int k = idx & 15;
    int beg = g_rowptr[n], end = g_rowptr[n + 1];
    float a0 = 0.f, a1 = 0.f;
    int e = beg;
    for (; e + 2 <= end; e += 2) {
        int i0 = g_eid[e], i1 = g_eid[e + 1];
        a0 += eattr[(size_t)i0 * EF + k];
        a1 += eattr[(size_t)i1 * EF + k];
    }
    if (e < end) a0 += eattr[(size_t)g_eid[e] * EF + k];
    g_ea[(size_t)n * EF + k] = a0 + a1;
}

// ---------- aggregate (standalone, high occupancy): x = h + deg*be + ea@We
// ---------- + sum h[src] ; warp per node, MLP=8 on the edge loop -----------
__global__ void __launch_bounds__(256)
k_aggregate(const float* __restrict__ We, const float* __restrict__ be) {
    __shared__ float Wes[EF * CH];
    __shared__ float bes[CH];
    for (int i = threadIdx.x; i < EF * CH; i += blockDim.x) Wes[i] = We[i];
    if (threadIdx.x < CH) bes[threadIdx.x] = be[threadIdx.x];
    __syncthreads();

    int n = (blockIdx.x * blockDim.x + threadIdx.x) >> 5;
    if (n >= NN) return;
    int lane = threadIdx.x & 31;
    int c0 = lane * 4;

    float4 acc = *(const float4*)(g_h + (size_t)n * CH + c0);
    float4 ac2 = make_float4(0.f, 0.f, 0.f, 0.f);
    float4 ac3 = make_float4(0.f, 0.f, 0.f, 0.f);
    float4 ac4 = make_float4(0.f, 0.f, 0.f, 0.f);

    int beg = g_rowptr[n], end = g_rowptr[n + 1];
    float dg = (float)(end - beg);
    float4 b4 = *(const float4*)&bes[c0];
    acc.x += dg * b4.x; acc.y += dg * b4.y;
    acc.z += dg * b4.z; acc.w += dg * b4.w;

#pragma unroll
    for (int k = 0; k < EF; k++) {
        float ev = g_ea[(size_t)n * EF + k];
        float4 w = *(const float4*)&Wes[k * CH + c0];
        acc.x += ev * w.x; acc.y += ev * w.y;
        acc.z += ev * w.z; acc.w += ev * w.w;
    }

    int e = beg;
    for (; e + 8 <= end; e += 8) {
        int s0 = g_col[e],     s1 = g_col[e + 1];
        int s2 = g_col[e + 2], s3 = g_col[e + 3];
        int s4 = g_col[e + 4], s5 = g_col[e + 5];
        int s6 = g_col[e + 6], s7 = g_col[e + 7];
        float4 v0 = *(const float4*)(g_h + (size_t)s0 * CH + c0);
        float4 v1 = *(const float4*)(g_h + (size_t)s1 * CH + c0);
        float4 v2 = *(const float4*)(g_h + (size_t)s2 * CH + c0);
        float4 v3 = *(const float4*)(g_h + (size_t)s3 * CH + c0);
        float4 v4 = *(const float4*)(g_h + (size_t)s4 * CH + c0);
        float4 v5 = *(const float4*)(g_h + (size_t)s5 * CH + c0);
        float4 v6 = *(const float4*)(g_h + (size_t)s6 * CH + c0);
        float4 v7 = *(const float4*)(g_h + (size_t)s7 * CH + c0);
        acc.x += v0.x + v1.x; ac2.x += v2.x + v3.x;
        ac3.x += v4.x + v5.x; ac4.x += v6.x + v7.x;
        acc.y += v0.y + v1.y; ac2.y += v2.y + v3.y;
        ac3.y += v4.y + v5.y; ac4.y += v6.y + v7.y;
        acc.z += v0.z + v1.z; ac2.z += v2.z + v3.z;
        ac3.z += v4.z + v5.z; ac4.z += v6.z + v7.z;
        acc.w += v0.w + v1.w; ac2.w += v2.w + v3.w;
        ac3.w += v4.w + v5.w; ac4.w += v6.w + v7.w;
    }
    for (; e + 2 <= end; e += 2) {
        int s0 = g_col[e], s1 = g_col[e + 1];
        float4 v0 = *(const float4*)(g_h + (size_t)s0 * CH + c0);
        float4 v1 = *(const float4*)(g_h + (size_t)s1 * CH + c0);
        ac2.x += v0.x + v1.x; ac2.y += v0.y + v1.y;
        ac2.z += v0.z + v1.z; ac2.w += v0.w + v1.w;
    }
    if (e < end) {
        int s = g_col[e];
        float4 v = *(const float4*)(g_h + (size_t)s * CH + c0);
        ac3.x += v.x; ac3.y += v.y; ac3.z += v.z; ac3.w += v.w;
    }
    acc.x += (ac2.x + ac3.x) + ac4.x;
    acc.y += (ac2.y + ac3.y) + ac4.y;
    acc.z += (ac2.z + ac3.z) + ac4.z;
    acc.w += (ac2.w + ac3.w) + ac4.w;

    *(float4*)(g_x + (size_t)n * CH + c0) = acc;
}

// ===================== GEMM core: 8 rows/warp, 4 cols/lane ==================
template <bool STATS>
__device__ __forceinline__ void gemm_tile8(
    const float* __restrict__ Ws, const float* __restrict__ xs,
    unsigned long long bias0, unsigned long long bias1,
    int tile, int r0, int c0, float* __restrict__ Z,
    float* cs, float* cq) {

    unsigned long long acc[TR][2];
#pragma unroll
    for (int r = 0; r < TR; r++) { acc[r][0] = bias0; acc[r][1] = bias1; }

#pragma unroll 2
    for (int k = 0; k < CH; k += 4) {
        float4 xv[TR];
#pragma unroll
        for (int r = 0; r < TR; r++) xv[r] = *(const float4*)&xs[(r0 + r) * CH + k];
#pragma unroll
        for (int kk = 0; kk < 4; kk++) {
            ulonglong2 w2 = *(const ulonglong2*)&Ws[(k + kk) * CH + c0];
#pragma unroll
            for (int r = 0; r < TR; r++) {
                float xr = (kk == 0) ? xv[r].x : (kk == 1) ? xv[r].y
                         : (kk == 2) ? xv[r].z : xv[r].w;
                unsigned long long xp;
                PACK_DUP(xp, xr);
                FMA2(acc[r][0], xp, w2.x);
                FMA2(acc[r][1], xp, w2.y);
            }
        }
    }

#pragma unroll
    for (int r = 0; r < TR; r++) {
        int m = tile + r0 + r;
        if (m < NN) {
            ulonglong2 o;
            o.x = acc[r][0]; o.y = acc[r][1];
            *(ulonglong2*)(Z + (size_t)m * CH + c0) = o;
            if (STATS) {
                float a0 = __uint_as_float((unsigned)acc[r][0]);
                float a1 = __uint_as_float((unsigned)(acc[r][0] >> 32));
                float a2 = __uint_as_float((unsigned)acc[r][1]);
                float a3 = __uint_as_float((unsigned)(acc[r][1] >> 32));
                cs[0] += a0; cq[0] += a0 * a0;
                cs[1] += a1; cq[1] += a1 * a1;
                cs[2] += a2; cq[2] += a2 * a2;
                cs[3] += a3; cq[3] += a3 * a3;
            }
        }
    }
}

// ------------------------- GEMM: Z = X@W + b (+ optional BN stats) ----------
template <bool STATS>
__global__ void __launch_bounds__(256, 2)
k_gemm(const float* __restrict__ X, const float* __restrict__ W,
       const float* __restrict__ B, float* __restrict__ Z,
       float* __restrict__ stats) {
    extern __shared__ float sm[];
    float* Ws = sm;                  // 128*128
    float* bs = Ws + CH * CH;        // 128
    float* xs = bs + CH;             // TILE*128

    for (int i = threadIdx.x; i < CH * CH; i += 256) Ws[i] = W[i];
    if (threadIdx.x < CH) bs[threadIdx.x] = B[threadIdx.x];
    __syncthreads();

    int warp = threadIdx.x >> 5, lane = threadIdx.x & 31;
    int c0 = lane * 4, r0 = warp * TR;
    unsigned long long bias0 = *(const unsigned long long*)&bs[c0];
    unsigned long long bias1 = *(const unsigned long long*)&bs[c0 + 2];
    float cs[4] = {0.f, 0.f, 0.f, 0.f};
    float cq[4] = {0.f, 0.f, 0.f, 0.f};

    for (int tile = blockIdx.x * TILE; tile < NN; tile += gridDim.x * TILE) {
#pragma unroll
        for (int r = 0; r < TR; r++) {
            int m = tile + r0 + r;
            float4 v = make_float4(0.f, 0.f, 0.f, 0.f);
            if (m < NN) v = *(const float4*)(X + (size_t)m * CH + c0);
            *(float4*)&xs[(r0 + r) * CH + c0] = v;
        }
        __syncwarp();   // warp-private slice: intra-warp ordering only
        gemm_tile8<STATS>(Ws, xs, bias0, bias1, tile, r0, c0, Z, cs, cq);
        __syncwarp();   // WAR before next overwrite
    }

    if (STATS) {
        __syncthreads();
        float* sr = xs;
        sr[threadIdx.x] = 0.f;
        __syncthreads();
#pragma unroll
        for (int j = 0; j < 4; j++) {
            atomicAdd(&sr[c0 + j], cs[j]);
            atomicAdd(&sr[CH + c0 + j], cq[j]);
        }
        __syncthreads();
        atomicAdd(&stats[threadIdx.x], sr[threadIdx.x]);
    }
}

// --- BN(from stats) + relu + residual + partial pool: grid (GG, 4) ---------
__global__ void k_poolbn(const float* __restrict__ stats,
                         const float* __restrict__ gamma,
                         const float* __restrict__ beta,
                         const int* __restrict__ batch,
                         float* __restrict__ pooled) {
    __shared__ int s_lo, s_hi;
    int g = blockIdx.x, part = blockIdx.y, c = threadIdx.x;

    float mu = stats[c] * (1.0f / NN);
    float var = stats[CH + c] * (1.0f / NN) - mu * mu;
    float sc = gamma[c] * rsqrtf(var + BN_EPS);
    float sh = beta[c] - mu * sc;

    if (c < 2) {
        int tgt = g + c;
        int lo = 0, hi = NN;
        while (lo < hi) {
            int mid = (lo + hi) >> 1;
            if (batch[mid] < tgt) lo = mid + 1; else hi = mid;
        }
        if (c == 0) s_lo = lo; else s_hi = lo;
    }
    __syncthreads();
    int gs = s_lo, ge = s_hi;
    int len = ge - gs;
    int per = (len + 3) >> 2;
    int lo = gs + part * per;
    int hi = lo + per; if (hi > ge) hi = ge;
    if (lo >= hi) { return; }

    float a0 = 0.f, a1 = 0.f;
    int n = lo;
    for (; n + 2 <= hi; n += 2) {
        float z0 = g_z[(size_t)n * CH + c];
        float h0 = g_h[(size_t)n * CH + c];
        float z1 = g_z[(size_t)(n + 1) * CH + c];
        float h1 = g_h[(size_t)(n + 1) * CH + c];
        float o0 = fmaxf(fmaf(z0, sc, sh), 0.f) + h0;
        float o1 = fmaxf(fmaf(z1, sc, sh), 0.f) + h1;
        g_h[(size_t)n * CH + c] = o0;
        g_h[(size_t)(n + 1) * CH + c] = o1;
        a0 += o0; a1 += o1;
    }
    if (n < hi) {
        float z0 = g_z[(size_t)n * CH + c];
        float h0 = g_h[(size_t)n * CH + c];
        float o0 = fmaxf(fmaf(z0, sc, sh), 0.f) + h0;
        g_h[(size_t)n * CH + c] = o0;
        a0 += o0;
    }
    atomicAdd(&pooled[(size_t)g * CH + c], a0 + a1);
}

// ------------------------- pool layer 0: grid (GG, 4) ----------------------
__global__ void k_pool0(const int* __restrict__ batch, float* __restrict__ pooled) {
    __shared__ int s_lo, s_hi;
    int g = blockIdx.x, part = blockIdx.y, c = threadIdx.x;
    if (c < 2) {
        int tgt = g + c;
        int lo = 0, hi = NN;
        while (lo < hi) {
            int mid = (lo + hi) >> 1;
            if (batch[mid] < tgt) lo = mid + 1; else hi = mid;
        }
        if (c == 0) s_lo = lo; else s_hi = lo;
    }
    __syncthreads();
    int gs = s_lo, ge = s_hi;
    int len = ge - gs;
    int per = (len + 3) >> 2;
    int lo = gs + part * per;
    int hi = lo + per; if (hi > ge) hi = ge;
    if (lo >= hi) return;

    float a0 = 0.f, a1 = 0.f;
    int n = lo;
    for (; n + 2 <= hi; n += 2) {
        a0 += g_h[(size_t)n * CH + c];
        a1 += g_h[(size_t)(n + 1) * CH + c];
    }
    if (n < hi) a0 += g_h[(size_t)n * CH + c];
    atomicAdd(&pooled[(size_t)g * CH + c], a0 + a1);
}

// ------------------------- JK heads ----------------------------------------
__global__ void k_jk(const float* __restrict__ jkW, const float* __restrict__ jkb,
                     float* __restrict__ out) {
    int idx = blockIdx.x * blockDim.x + threadIdx.x;
    if (idx >= GG * NC) return;
    int g = idx / NC, c = idx % NC;
    float acc = 0.f;
#pragma unroll
    for (int l = 0; l < NL + 1; l++) {
        acc += jkb[l * NC + c];
        const float* p = g_pooled + ((size_t)l * GG + g) * CH;
        const float* w = jkW + l * CH * NC + c;
        float a = 0.f;
#pragma unroll 8
        for (int k = 0; k < CH; k++) a += p[k] * w[k * NC];
        acc += a;
    }
    out[idx] = acc;
}

// ------------------------- host launch -------------------------------------
extern "C" void kernel_launch(void* const* d_in, const int* in_sizes, int n_in,
                              void* d_out, int out_size) {
    (void)in_sizes; (void)n_in; (void)out_size;
    const float* h_in   = (const float*)d_in[0];
    const float* eattr  = (const float*)d_in[1];
    const int*   ei     = (const int*)d_in[2];
    const int*   batch  = (const int*)d_in[5];
    const float* embW   = (const float*)d_in[6];
    const float* embB   = (const float*)d_in[7];
    const float* convW  = (const float*)d_in[8];
    const float* convB  = (const float*)d_in[9];
    const float* convWe = (const float*)d_in[10];
    const float* convBe = (const float*)d_in[11];
    const float* gamma  = (const float*)d_in[12];
    const float* beta   = (const float*)d_in[13];
    const float* jkW    = (const float*)d_in[14];
    const float* jkb    = (const float*)d_in[15];
    float* out = (float*)d_out;

    void *p_deg, *p_pooled, *p_stats, *p_h, *p_x, *p_z;
    cudaGetSymbolAddress(&p_deg, g_deg);
    cudaGetSymbolAddress(&p_pooled, g_pooled);
    cudaGetSymbolAddress(&p_stats, g_stats);
    cudaGetSymbolAddress(&p_h, g_h);
    cudaGetSymbolAddress(&p_x, g_x);
    cudaGetSymbolAddress(&p_z, g_z);

    const int smem_g = (CH * CH + CH + TILE * CH) * (int)sizeof(float);
    cudaFuncSetAttribute(k_gemm<false>, cudaFuncAttributeMaxDynamicSharedMemorySize, smem_g);
    cudaFuncSetAttribute(k_gemm<true>, cudaFuncAttributeMaxDynamicSharedMemorySize, smem_g);

    cudaMemsetAsync(p_deg, 0, NN * sizeof(int));
    cudaMemsetAsync(p_stats, 0, NL * 2 * CH * sizeof(float));
    cudaMemsetAsync(p_pooled, 0, (NL + 1) * GG * CH * sizeof(float));

    const int nb = (NN + 1023) / 1024;  // 49
    k_deg<<<(EE + 255) / 256, 256>>>(ei);                                 // k1
    k_scan1<<<nb, 1024>>>();                                              // k2
    k_scan3<<<nb, 1024>>>(nb);                                            // k3
    k_gemm<false><<<296, 256, smem_g>>>(h_in, embW, embB, (float*)p_h, nullptr); // k4 (profiled)
    k_fill<<<(EE + 255) / 256, 256>>>(ei);
    k_ea<<<(NN * 16 + 255) / 256, 256>>>(eattr);
    k_pool0<<<dim3(GG, 4), CH>>>(batch, (float*)p_pooled);

    for (int l = 0; l < NL; l++) {
        k_aggregate<<<(NN * 32 + 255) / 256, 256>>>(convWe + (size_t)l * EF * CH,
                                                    convBe + (size_t)l * CH);
        k_gemm<true><<<296, 256, smem_g>>>((const float*)p_x,
                                           convW + (size_t)l * CH * CH,
                                           convB + (size_t)l * CH,
                                           (float*)p_z,
                                           (float*)p_stats + (size_t)l * 2 * CH);
        k_poolbn<<<dim3(GG, 4), CH>>>((const float*)p_stats + (size_t)l * 2 * CH,
                                      gamma + (size_t)l * CH, beta + (size_t)l * CH,
                                      batch, (float*)p_pooled + (size_t)(l + 1) * GG * CH);
    }

    k_jk<<<(GG * NC + 255) / 256, 256>>>(jkW, jkb, out);
}